// round 4
// baseline (speedup 1.0000x reference)
#include <cuda_runtime.h>
#include <cuda_bf16.h>
#include <math.h>

#define NN 100000
#define NE 3200000
#define MAXD 256

// ---------------- static device scratch (allocation-free contract) ----------------
__device__ float g_bufA[(size_t)NN * MAXD];
__device__ float g_bufB[(size_t)NN * MAXD];
__device__ float g_bufC[(size_t)NN * MAXD];
__device__ int   g_src[NE];
__device__ int   g_dst[NE];
__device__ int   g_cnt[NN];        // invariant: zero at entry of kernel_launch
__device__ int   g_rowptr[NN + 1];
__device__ int   g_woff[NN];
__device__ int2  g_csre[NE];       // packed {src, weight-bits}
__device__ float g_di[NN];
__device__ float g_dis[NN];
__device__ float g_bn[512];        // invariant: zero at entry (finalize re-zeroes)
__device__ float g_scale[256];
__device__ float g_shift[256];

// ---------------- prep: detect dtype inline, convert, count in-degree ----------------
__global__ void k_prep_edges(const void* __restrict__ ei_raw,
                             int* __restrict__ src, int* __restrict__ dst,
                             int* __restrict__ cnt, int E, int n) {
    const unsigned int* w = (const unsigned int*)ei_raw;
    unsigned int probe = w[2 * (threadIdx.x & 255) + 1];
    int any = __syncthreads_or(probe != 0u);
    const int is64 = (any == 0);
    const long long* ei64 = (const long long*)ei_raw;
    const int* ei32 = (const int*)ei_raw;
    for (int e = blockIdx.x * blockDim.x + threadIdx.x; e < E; e += gridDim.x * blockDim.x) {
        int s, d;
        if (is64) { s = (int)ei64[e]; d = (int)ei64[(size_t)E + e]; }
        else      { s = ei32[e];      d = ei32[(size_t)E + e]; }
        if ((unsigned)s >= (unsigned)n) s = 0;
        if ((unsigned)d >= (unsigned)n) d = 0;
        src[e] = s;
        dst[e] = d;
        atomicAdd(&cnt[d], 1);
    }
}

// ---------------- single-block tiled coalesced scan + deg + cnt re-zero ----------------
__global__ void k_scan_deg(int* __restrict__ cnt, int* __restrict__ rowptr,
                           int* __restrict__ woff, float* __restrict__ di,
                           float* __restrict__ dis, int n) {
    __shared__ int wsum[32];
    __shared__ int s_off;
    int t = threadIdx.x, lane = t & 31, wid = t >> 5;
    if (t == 0) s_off = 0;
    __syncthreads();
    for (int base = 0; base < n; base += 1024) {
        int i = base + t;
        int c = (i < n) ? cnt[i] : 0;
        if (i < n) cnt[i] = 0;
        int x = c;
#pragma unroll
        for (int o = 1; o < 32; o <<= 1) {
            int v = __shfl_up_sync(0xffffffffu, x, o);
            if (lane >= o) x += v;
        }
        if (lane == 31) wsum[wid] = x;
        __syncthreads();
        if (wid == 0) {
            int y = wsum[lane];
#pragma unroll
            for (int o = 1; o < 32; o <<= 1) {
                int v = __shfl_up_sync(0xffffffffu, y, o);
                if (lane >= o) y += v;
            }
            wsum[lane] = y;
        }
        __syncthreads();
        int wbase = (wid == 0) ? 0 : wsum[wid - 1];
        int excl = x + wbase - c;
        int off0 = s_off;
        if (i < n) {
            int r = off0 + excl;
            rowptr[i] = r;
            woff[i]   = r;
            float dg = (float)c + 1.0f;
            di[i]  = 1.0f / dg;
            dis[i] = rsqrtf(dg);
        }
        __syncthreads();
        if (t == 1023) s_off = off0 + wsum[31];
        __syncthreads();
    }
    if (t == 0) rowptr[n] = s_off;
}

// ---------------- CSR scatter with packed (src, weight) ----------------
__global__ void k_csr(const int* __restrict__ src, const int* __restrict__ dst,
                      const float* __restrict__ dis, int* __restrict__ woff,
                      int2* __restrict__ csre, int E) {
    for (int e = blockIdx.x * blockDim.x + threadIdx.x; e < E; e += gridDim.x * blockDim.x) {
        int d = dst[e];
        int pos = atomicAdd(&woff[d], 1);
        int s = src[e];
        if (pos < E) {
            float w = dis[s] * dis[d];
            csre[pos] = make_int2(s, __float_as_int(w));
        }
    }
}

// ---------------- aggregation: warp-per-node gather, 4-edge unroll ----------------
template <int D, bool EPI, bool AFF>
__global__ __launch_bounds__(256) void k_agg(
    const float* __restrict__ xin, float* __restrict__ xout,
    const int* __restrict__ rowptr, const int2* __restrict__ csre,
    const float* __restrict__ di, int n,
    const float* __restrict__ scale, const float* __restrict__ shift,
    const float* __restrict__ bias, float* __restrict__ bnsum, float* __restrict__ bnsq)
{
    constexpr int CPL = D / 32;
    int lane = threadIdx.x & 31;
    int node = blockIdx.x * 8 + (threadIdx.x >> 5);
    float acc[CPL];
    float sc[CPL], sh[CPL];
#pragma unroll
    for (int j = 0; j < CPL; j++) {
        acc[j] = 0.f;
        if (AFF) { sc[j] = scale[lane + 32 * j]; sh[j] = shift[lane + 32 * j]; }
    }

    if (node < n) {
        int beg = rowptr[node], end = rowptr[node + 1];
        int e = beg;
        for (; e + 4 <= end; e += 4) {
            int2 p0 = __ldg(&csre[e]);
            int2 p1 = __ldg(&csre[e + 1]);
            int2 p2 = __ldg(&csre[e + 2]);
            int2 p3 = __ldg(&csre[e + 3]);
            const float* r0 = xin + (size_t)p0.x * D + lane;
            const float* r1 = xin + (size_t)p1.x * D + lane;
            const float* r2 = xin + (size_t)p2.x * D + lane;
            const float* r3 = xin + (size_t)p3.x * D + lane;
            float v0[CPL], v1[CPL], v2[CPL], v3[CPL];
#pragma unroll
            for (int j = 0; j < CPL; j++) v0[j] = __ldg(r0 + 32 * j);
#pragma unroll
            for (int j = 0; j < CPL; j++) v1[j] = __ldg(r1 + 32 * j);
#pragma unroll
            for (int j = 0; j < CPL; j++) v2[j] = __ldg(r2 + 32 * j);
#pragma unroll
            for (int j = 0; j < CPL; j++) v3[j] = __ldg(r3 + 32 * j);
            float w0 = __int_as_float(p0.y), w1 = __int_as_float(p1.y);
            float w2 = __int_as_float(p2.y), w3 = __int_as_float(p3.y);
#pragma unroll
            for (int j = 0; j < CPL; j++) {
                float a0 = AFF ? fmaxf(v0[j] * sc[j] + sh[j], 0.f) : v0[j];
                float a1 = AFF ? fmaxf(v1[j] * sc[j] + sh[j], 0.f) : v1[j];
                float a2 = AFF ? fmaxf(v2[j] * sc[j] + sh[j], 0.f) : v2[j];
                float a3 = AFF ? fmaxf(v3[j] * sc[j] + sh[j], 0.f) : v3[j];
                acc[j] += w0 * a0 + w1 * a1;
                acc[j] += w2 * a2 + w3 * a3;
            }
        }
        for (; e < end; e++) {
            int2 p0 = __ldg(&csre[e]);
            float w0 = __int_as_float(p0.y);
            const float* r0 = xin + (size_t)p0.x * D + lane;
#pragma unroll
            for (int j = 0; j < CPL; j++) {
                float v = __ldg(r0 + 32 * j);
                float a = AFF ? fmaxf(v * sc[j] + sh[j], 0.f) : v;
                acc[j] += w0 * a;
            }
        }
        float dii = di[node];
        const float* r = xin + (size_t)node * D + lane;
#pragma unroll
        for (int j = 0; j < CPL; j++) {
            float v = __ldg(r + 32 * j);
            float a = AFF ? fmaxf(v * sc[j] + sh[j], 0.f) : v;
            acc[j] += dii * a;
            if (EPI) acc[j] += bias[lane + 32 * j];
            xout[(size_t)node * D + lane + 32 * j] = acc[j];
        }
    }
    if constexpr (EPI) {
        __shared__ float csum[D];
        __shared__ float csq[D];
        for (int t = threadIdx.x; t < D; t += blockDim.x) { csum[t] = 0.f; csq[t] = 0.f; }
        __syncthreads();
        if (node < n) {
#pragma unroll
            for (int j = 0; j < CPL; j++) {
                atomicAdd(&csum[lane + 32 * j], acc[j]);
                atomicAdd(&csq[lane + 32 * j], acc[j] * acc[j]);
            }
        }
        __syncthreads();
        for (int t = threadIdx.x; t < D; t += blockDim.x) {
            atomicAdd(&bnsum[t], csum[t]);
            atomicAdd(&bnsq[t], csq[t]);
        }
    }
}

// ---------------- bf16x2-split tensor-core GEMM ----------------
// C[M,Nc] = act(A)[M,K] @ W[K,Nc] via 3 bf16 MMAs (Ah*Bh + Ah*Bl + Al*Bh)
__device__ __forceinline__ void cvt_pair(float x0, float x1, unsigned& hi, unsigned& lo) {
    __nv_bfloat16 h0 = __float2bfloat16_rn(x0);
    __nv_bfloat16 h1 = __float2bfloat16_rn(x1);
    float r0 = x0 - __bfloat162float(h0);
    float r1 = x1 - __bfloat162float(h1);
    __nv_bfloat162 H; H.x = h0; H.y = h1;
    __nv_bfloat162 L; L.x = __float2bfloat16_rn(r0); L.y = __float2bfloat16_rn(r1);
    hi = *reinterpret_cast<unsigned*>(&H);
    lo = *reinterpret_cast<unsigned*>(&L);
}

#define MMA_BF16(c, a, b)                                                              \
    asm volatile(                                                                      \
        "mma.sync.aligned.m16n8k16.row.col.f32.bf16.bf16.f32 "                         \
        "{%0,%1,%2,%3},{%4,%5,%6,%7},{%8,%9},{%0,%1,%2,%3};"                           \
        : "+f"((c)[0]), "+f"((c)[1]), "+f"((c)[2]), "+f"((c)[3])                       \
        : "r"((a)[0]), "r"((a)[1]), "r"((a)[2]), "r"((a)[3]), "r"((b)[0]), "r"((b)[1]))

template <bool EPI, bool AFF>
__global__ __launch_bounds__(256) void k_gemm_tc(
    const float* __restrict__ A, const float* __restrict__ W, float* __restrict__ C,
    int M, int K, int Nc,
    const float* __restrict__ scale, const float* __restrict__ shift,
    const float* __restrict__ bias, float* __restrict__ bnsum, float* __restrict__ bnsq)
{
    __shared__ unsigned AsH[128][8], AsL[128][8];   // [m][k-pair]
    __shared__ unsigned BsH[64][8],  BsL[64][8];    // [n][k-pair]
    int tid = threadIdx.x;
    int row0 = blockIdx.y * 128, col0 = blockIdx.x * 64;
    int w = tid >> 5, lane = tid & 31;
    int wm = w & 3, wn = w >> 2;        // 4x2 warp grid -> warp tile 32x32
    int g = lane >> 2, t = lane & 3;

    float acc[2][4][4];
#pragma unroll
    for (int mi = 0; mi < 2; mi++)
#pragma unroll
        for (int ni = 0; ni < 4; ni++)
#pragma unroll
            for (int q = 0; q < 4; q++) acc[mi][ni][q] = 0.f;

    int am_ld = tid >> 1;               // 0..127
    int ak_ld = (tid & 1) * 8;          // 0 or 8
    int bn_ld = tid >> 2;               // 0..63
    int bk_ld = (tid & 3) * 4;          // 0,4,8,12

    for (int k0 = 0; k0 < K; k0 += 16) {
        // --- stage A tile 128x16 (fused affine+relu) ---
        {
            int gm = row0 + am_ld;
            float v[8];
            if (gm < M) {
                float4 p = *(const float4*)(A + (size_t)gm * K + k0 + ak_ld);
                float4 q = *(const float4*)(A + (size_t)gm * K + k0 + ak_ld + 4);
                v[0] = p.x; v[1] = p.y; v[2] = p.z; v[3] = p.w;
                v[4] = q.x; v[5] = q.y; v[6] = q.z; v[7] = q.w;
            } else {
#pragma unroll
                for (int i = 0; i < 8; i++) v[i] = 0.f;
            }
            if (AFF) {
#pragma unroll
                for (int i = 0; i < 8; i++) {
                    int kk = k0 + ak_ld + i;
                    v[i] = fmaxf(v[i] * scale[kk] + shift[kk], 0.f);
                }
            }
#pragma unroll
            for (int i = 0; i < 4; i++) {
                unsigned h, l;
                cvt_pair(v[2 * i], v[2 * i + 1], h, l);
                AsH[am_ld][ak_ld / 2 + i] = h;
                AsL[am_ld][ak_ld / 2 + i] = l;
            }
        }
        // --- stage B tile (W transposed to [n][k]) 64x16 ---
        {
            int gc = col0 + bn_ld;
            float v[4];
#pragma unroll
            for (int j = 0; j < 4; j++)
                v[j] = (gc < Nc) ? W[(size_t)(k0 + bk_ld + j) * Nc + gc] : 0.f;
#pragma unroll
            for (int i = 0; i < 2; i++) {
                unsigned h, l;
                cvt_pair(v[2 * i], v[2 * i + 1], h, l);
                BsH[bn_ld][bk_ld / 2 + i] = h;
                BsL[bn_ld][bk_ld / 2 + i] = l;
            }
        }
        __syncthreads();
        // --- fragments + mma ---
        unsigned aH[2][4], aL[2][4], bH[4][2], bL[4][2];
#pragma unroll
        for (int mi = 0; mi < 2; mi++) {
            int r = wm * 32 + mi * 16;
            aH[mi][0] = AsH[r + g][t];       aL[mi][0] = AsL[r + g][t];
            aH[mi][1] = AsH[r + g + 8][t];   aL[mi][1] = AsL[r + g + 8][t];
            aH[mi][2] = AsH[r + g][t + 4];   aL[mi][2] = AsL[r + g][t + 4];
            aH[mi][3] = AsH[r + g + 8][t + 4]; aL[mi][3] = AsL[r + g + 8][t + 4];
        }
#pragma unroll
        for (int ni = 0; ni < 4; ni++) {
            int c = wn * 32 + ni * 8;
            bH[ni][0] = BsH[c + g][t];     bL[ni][0] = BsL[c + g][t];
            bH[ni][1] = BsH[c + g][t + 4]; bL[ni][1] = BsL[c + g][t + 4];
        }
#pragma unroll
        for (int mi = 0; mi < 2; mi++)
#pragma unroll
            for (int ni = 0; ni < 4; ni++) {
                MMA_BF16(acc[mi][ni], aH[mi], bH[ni]);
                MMA_BF16(acc[mi][ni], aH[mi], bL[ni]);
                MMA_BF16(acc[mi][ni], aL[mi], bH[ni]);
            }
        __syncthreads();
    }

    // --- epilogue ---
    if constexpr (!EPI) {
#pragma unroll
        for (int mi = 0; mi < 2; mi++) {
            int rt = row0 + wm * 32 + mi * 16 + g;
#pragma unroll
            for (int ni = 0; ni < 4; ni++) {
                int gc = col0 + wn * 32 + ni * 8 + 2 * t;
                if (gc < Nc) {
                    if (rt < M)
                        *(float2*)(C + (size_t)rt * Nc + gc) =
                            make_float2(acc[mi][ni][0], acc[mi][ni][1]);
                    if (rt + 8 < M)
                        *(float2*)(C + (size_t)(rt + 8) * Nc + gc) =
                            make_float2(acc[mi][ni][2], acc[mi][ni][3]);
                }
            }
        }
    } else {
        __shared__ float csum[64];
        __shared__ float csq[64];
        if (tid < 64) { csum[tid] = 0.f; csq[tid] = 0.f; }
        __syncthreads();
#pragma unroll
        for (int ni = 0; ni < 4; ni++) {
            int cl = wn * 32 + ni * 8 + 2 * t;
            int gc = col0 + cl;
            if (gc >= Nc) continue;
            float b0 = bias[gc], b1 = bias[gc + 1];
            float s0 = 0.f, s1 = 0.f, q0 = 0.f, q1 = 0.f;
#pragma unroll
            for (int mi = 0; mi < 2; mi++) {
                int rt = row0 + wm * 32 + mi * 16 + g;
                if (rt < M) {
                    float v0 = acc[mi][ni][0] + b0;
                    float v1 = acc[mi][ni][1] + b1;
                    *(float2*)(C + (size_t)rt * Nc + gc) = make_float2(v0, v1);
                    s0 += v0; s1 += v1; q0 += v0 * v0; q1 += v1 * v1;
                }
                if (rt + 8 < M) {
                    float v2 = acc[mi][ni][2] + b0;
                    float v3 = acc[mi][ni][3] + b1;
                    *(float2*)(C + (size_t)(rt + 8) * Nc + gc) = make_float2(v2, v3);
                    s0 += v2; s1 += v3; q0 += v2 * v2; q1 += v3 * v3;
                }
            }
            atomicAdd(&csum[cl], s0);
            atomicAdd(&csum[cl + 1], s1);
            atomicAdd(&csq[cl], q0);
            atomicAdd(&csq[cl + 1], q1);
        }
        __syncthreads();
        if (tid < 64 && col0 + tid < Nc) {
            atomicAdd(&bnsum[col0 + tid], csum[tid]);
            atomicAdd(&bnsq[col0 + tid], csq[tid]);
        }
    }
}

// ---------------- BN finalize: scale/shift from stats, then re-zero stats ----------------
__global__ void k_bn_finalize(const float* __restrict__ g, const float* __restrict__ be,
                              int d, float invN, float* __restrict__ bn,
                              float* __restrict__ scale, float* __restrict__ shift) {
    int t = threadIdx.x;
    float s = bn[t], q = bn[256 + t];
    if (t < d) {
        float mu  = s * invN;
        float var = q * invN - mu * mu;
        float rstd = rsqrtf(fmaxf(var, 0.f) + 1e-5f);
        float sc = g[t] * rstd;
        scale[t] = sc;
        shift[t] = be[t] - mu * sc;
    }
    bn[t] = 0.f;
    bn[256 + t] = 0.f;
}

// ---------------- edge head: 2 edges per warp, fused affine+relu ----------------
__global__ __launch_bounds__(256) void k_edge_out(
    const float* __restrict__ conv, const int* __restrict__ src, const int* __restrict__ dst,
    const float* __restrict__ scale, const float* __restrict__ shift,
    const float* __restrict__ fcw, const float* __restrict__ fcb,
    float* __restrict__ out, int E)
{
    int warp = (blockIdx.x * blockDim.x + threadIdx.x) >> 5;
    int lane = threadIdx.x & 31;
    int half = lane >> 4;
    int l16  = lane & 15;
    int eid = warp * 2 + half;
    if (eid >= E) return;
    int s = src[eid], d = dst[eid];
    const float* rs = conv + (size_t)s * 32;
    const float* rd = conv + (size_t)d * 32;
    float v = 0.f;
#pragma unroll
    for (int p = 0; p < 2; p++) {
        int f = l16 + 16 * p;
        float sc = scale[f], sh = shift[f];
        float a = fmaxf(__ldg(rs + f) * sc + sh, 0.f);
        float b = fmaxf(__ldg(rd + f) * sc + sh, 0.f);
        v += a * b * fcw[f];
    }
#pragma unroll
    for (int o = 8; o; o >>= 1) v += __shfl_xor_sync(0xffffffffu, v, o);
    if (l16 == 0) out[eid] = 1.f / (1.f + expf(-(v + fcb[0])));
}

// ---------------- host ----------------
extern "C" void kernel_launch(void* const* d_in, const int* in_sizes, int n_in,
                              void* d_out, int out_size)
{
    const float* x0 = (const float*)d_in[0];
    const void* ei = d_in[1];
    const float *Wl[5], *bl[5], *gl[5], *bel[5];
    for (int l = 0; l < 5; l++) {
        Wl[l]  = (const float*)d_in[2 + 4 * l];
        bl[l]  = (const float*)d_in[3 + 4 * l];
        gl[l]  = (const float*)d_in[4 + 4 * l];
        bel[l] = (const float*)d_in[5 + 4 * l];
    }
    const float* fcw = (const float*)d_in[22];
    const float* fcb = (const float*)d_in[23];
    float* out = (float*)d_out;
    const int n = NN, E = NE;
    (void)in_sizes; (void)n_in; (void)out_size;

    float *bufA, *bufB, *bufC, *di, *dis, *bn, *scale, *shift;
    int *src, *dst, *cnt, *rowptr, *woff;
    int2* csre;
    cudaGetSymbolAddress((void**)&bufA,  g_bufA);
    cudaGetSymbolAddress((void**)&bufB,  g_bufB);
    cudaGetSymbolAddress((void**)&bufC,  g_bufC);
    cudaGetSymbolAddress((void**)&src,   g_src);
    cudaGetSymbolAddress((void**)&dst,   g_dst);
    cudaGetSymbolAddress((void**)&cnt,   g_cnt);
    cudaGetSymbolAddress((void**)&rowptr,g_rowptr);
    cudaGetSymbolAddress((void**)&woff,  g_woff);
    cudaGetSymbolAddress((void**)&csre,  g_csre);
    cudaGetSymbolAddress((void**)&di,    g_di);
    cudaGetSymbolAddress((void**)&dis,   g_dis);
    cudaGetSymbolAddress((void**)&bn,    g_bn);
    cudaGetSymbolAddress((void**)&scale, g_scale);
    cudaGetSymbolAddress((void**)&shift, g_shift);

    int aggBlocks = (n + 7) / 8;
    int rowBlocks = (n + 127) / 128;
    float invN = 1.0f / (float)n;

    k_prep_edges<<<2048, 256>>>(ei, src, dst, cnt, E, n);
    k_scan_deg<<<1, 1024>>>(cnt, rowptr, woff, di, dis, n);
    k_csr<<<2048, 256>>>(src, dst, dis, woff, csre, E);

    // L0 (agg-first)
    k_agg<128, false, false><<<aggBlocks, 256>>>(x0, bufB, rowptr, csre, di, n,
                                                 nullptr, nullptr, nullptr, nullptr, nullptr);
    k_gemm_tc<true, false><<<dim3(2, rowBlocks), 256>>>(bufB, Wl[0], bufC, n, 128, 128,
                                                        nullptr, nullptr, bl[0], bn, bn + 256);
    k_bn_finalize<<<1, 256>>>(gl[0], bel[0], 128, invN, bn, scale, shift);

    // L1 (agg-first)
    k_agg<128, false, true><<<aggBlocks, 256>>>(bufC, bufB, rowptr, csre, di, n,
                                                scale, shift, nullptr, nullptr, nullptr);
    k_gemm_tc<true, false><<<dim3(4, rowBlocks), 256>>>(bufB, Wl[1], bufA, n, 128, 256,
                                                        nullptr, nullptr, bl[1], bn, bn + 256);
    k_bn_finalize<<<1, 256>>>(gl[1], bel[1], 256, invN, bn, scale, shift);

    // L2 (gemm-first)
    k_gemm_tc<false, true><<<dim3(2, rowBlocks), 256>>>(bufA, Wl[2], bufB, n, 256, 128,
                                                        scale, shift, nullptr, nullptr, nullptr);
    k_agg<128, true, false><<<aggBlocks, 256>>>(bufB, bufC, rowptr, csre, di, n,
                                                nullptr, nullptr, bl[2], bn, bn + 256);
    k_bn_finalize<<<1, 256>>>(gl[2], bel[2], 128, invN, bn, scale, shift);

    // L3 (gemm-first)
    k_gemm_tc<false, true><<<dim3(1, rowBlocks), 256>>>(bufC, Wl[3], bufB, n, 128, 64,
                                                        scale, shift, nullptr, nullptr, nullptr);
    k_agg<64, true, false><<<aggBlocks, 256>>>(bufB, bufA, rowptr, csre, di, n,
                                               nullptr, nullptr, bl[3], bn, bn + 256);
    k_bn_finalize<<<1, 256>>>(gl[3], bel[3], 64, invN, bn, scale, shift);

    // L4 (gemm-first)
    k_gemm_tc<false, true><<<dim3(1, rowBlocks), 256>>>(bufA, Wl[4], bufB, n, 64, 32,
                                                        scale, shift, nullptr, nullptr, nullptr);
    k_agg<32, true, false><<<aggBlocks, 256>>>(bufB, bufC, rowptr, csre, di, n,
                                               nullptr, nullptr, bl[4], bn, bn + 256);
    k_bn_finalize<<<1, 256>>>(gl[4], bel[4], 32, invN, bn, scale, shift);

    // edge head
    int edgeBlocks = (E / 2 + 7) / 8;
    k_edge_out<<<edgeBlocks, 256>>>(bufC, src, dst, scale, shift, fcw, fcb, out, E);
}